// round 2
// baseline (speedup 1.0000x reference)
#include <cuda_runtime.h>
#include <stdint.h>

// ============================================================================
// L2Loss with class-rebalancing weights (colorization loss).
// Exact NN via uniform-grid LUT; per-cell candidates packed into ONE uint64
// (4 x u16, padded with duplicates of cand0; 0xFFFF in slot3 = overflow).
// Loss kernel: 4 px/thread, float4 loads, exact-compare argmin, block reduce.
// ============================================================================

#define LGRID 64
#define NCELL (LGRID * LGRID)
#define CAP   32
#define MAXQ  512   // shared-array capacity; actual Q = 313

__device__ unsigned long long g_pack[NCELL];
__device__ unsigned short     g_cand[NCELL * CAP];
__device__ unsigned int       g_cnt[NCELL];

// ---------------------------------------------------------------------------
// Build LUT: one warp per cell; 512 blocks x 256 threads = 4096 warps.
// Candidates = all bins with d(center,bin) <= dmin(center) + 2r  (r = half-diag)
// -> provably contains true NN for every point in the cell.
// Also zeroes the output scalar (runs before loss_kernel in-stream).
// ---------------------------------------------------------------------------
__global__ void __launch_bounds__(256) build_lut_kernel(
    const float2* __restrict__ gamut, int Q, float* __restrict__ out)
{
    __shared__ float2 sg[MAXQ];
    __shared__ unsigned short scand[8][CAP];
    for (int i = threadIdx.x; i < Q; i += blockDim.x) sg[i] = gamut[i];
    __syncthreads();

    if (blockIdx.x == 0 && threadIdx.x == 0) out[0] = 0.0f;

    const int warp = threadIdx.x >> 5;
    const int lane = threadIdx.x & 31;
    const int cell = blockIdx.x * 8 + warp;   // grid sized exactly: 512*8 = 4096

    const int ix = cell & (LGRID - 1);
    const int iy = cell >> 6;
    const float cellw = 2.0f / (float)LGRID;
    const float cx = -1.0f + ((float)ix + 0.5f) * cellw;
    const float cy = -1.0f + ((float)iy + 0.5f) * cellw;
    const float two_r = 0.04450f;   // full diagonal 0.044194 + FP pad

    float d2s[(MAXQ + 31) / 32];
    float dmin = 1e30f;
    const int nIter = (Q + 31) >> 5;
    #pragma unroll
    for (int j = 0; j < (MAXQ + 31) / 32; j++) {
        if (j >= nIter) break;
        const int b = (j << 5) + lane;
        float d2 = 1e30f;
        if (b < Q) {
            const float dx = sg[b].x - cx;
            const float dy = sg[b].y - cy;
            d2 = fmaf(dx, dx, dy * dy);
        }
        d2s[j] = d2;
        dmin = fminf(dmin, d2);
    }
    #pragma unroll
    for (int off = 16; off; off >>= 1)
        dmin = fminf(dmin, __shfl_xor_sync(0xFFFFFFFFu, dmin, off));

    const float s   = sqrtf(dmin) + two_r;
    const float thr = fmaf(s, s, 1e-6f) * 1.00002f;

    int base = 0;
    for (int j = 0; j < nIter; j++) {
        const bool take = (d2s[j] <= thr);
        const unsigned m = __ballot_sync(0xFFFFFFFFu, take);
        if (take) {
            const int pos = base + __popc(m & ((1u << lane) - 1u));
            if (pos < CAP)
                scand[warp][pos] = (unsigned short)((j << 5) + lane);
        }
        base += __popc(m);
    }
    __syncwarp();

    const int nw = min(base, CAP);
    for (int j = lane; j < nw; j += 32)
        g_cand[cell * CAP + j] = scand[warp][j];

    if (lane == 0) {
        g_cnt[cell] = (unsigned)base;
        const unsigned long long i0 = scand[warp][0];        // base >= 1 always
        const unsigned long long i1 = (base > 1) ? scand[warp][1] : i0;
        const unsigned long long i2 = (base > 2) ? scand[warp][2] : i0;
        unsigned long long i3       = (base > 3) ? scand[warp][3] : i0;
        if (base > 4) i3 = 0xFFFFull;                        // overflow sentinel
        g_pack[cell] = i0 | (i1 << 16) | (i2 << 32) | (i3 << 48);
    }
}

// ---------------------------------------------------------------------------
// Loss kernel: 65536 threads (256 blocks x 256), 4 consecutive pixels/thread.
// Layout [b, 2, 256, 256]: pixel q -> b = q>>16, n = q&65535,
//   ch0 at b*131072 + n, ch1 at +65536. n%4==0 per thread -> float4 aligned.
// score = -2 g.t + (|g|^2 + 16): same argmin as d2, exact strict-< compare,
// candidates in ascending index order -> lowest-index tie-break like argmin.
// ---------------------------------------------------------------------------
__global__ void __launch_bounds__(256) loss_kernel(
    const float*  __restrict__ input,
    const float*  __restrict__ target,
    const float2* __restrict__ gamut,
    const float*  __restrict__ prior,
    float*        __restrict__ out,
    int Q)
{
    __shared__ float4 sf[MAXQ];   // (ha=-2gx, hb=-2gy, c=|g|^2+16, prior)
    for (int i = threadIdx.x; i < Q; i += blockDim.x) {
        const float2 g = gamut[i];
        sf[i] = make_float4(-2.0f * g.x, -2.0f * g.y,
                            fmaf(g.x, g.x, fmaf(g.y, g.y, 16.0f)),
                            prior[i]);
    }
    __syncthreads();

    const int tid   = blockIdx.x * blockDim.x + threadIdx.x;  // 0..65535
    const int q     = tid << 2;
    const int bb    = q >> 16;
    const int n     = q & 65535;
    const int base0 = bb * 131072 + n;

    const float4 tv0 = *(const float4*)(target + base0);
    const float4 tv1 = *(const float4*)(target + base0 + 65536);
    const float4 iv0 = *(const float4*)(input  + base0);
    const float4 iv1 = *(const float4*)(input  + base0 + 65536);

    const float ta[4] = {tv0.x, tv0.y, tv0.z, tv0.w};
    const float tb[4] = {tv1.x, tv1.y, tv1.z, tv1.w};
    const float ia[4] = {iv0.x, iv0.y, iv0.z, iv0.w};
    const float ib[4] = {iv1.x, iv1.y, iv1.z, iv1.w};

    float acc = 0.0f;

    #pragma unroll
    for (int k = 0; k < 4; k++) {
        int ix = (int)((ta[k] + 1.0f) * ((float)LGRID * 0.5f));
        int iy = (int)((tb[k] + 1.0f) * ((float)LGRID * 0.5f));
        ix = min(max(ix, 0), LGRID - 1);
        iy = min(max(iy, 0), LGRID - 1);
        const int cell = (iy << 6) | ix;

        const unsigned long long p = g_pack[cell];
        const unsigned a0 = (unsigned)(p & 0xFFFFull);
        const unsigned a1 = (unsigned)((p >> 16) & 0xFFFFull);
        const unsigned a2 = (unsigned)((p >> 32) & 0xFFFFull);
        const unsigned a3 = (unsigned)(p >> 48);

        float    bestSc;
        unsigned bestIdx;

        if (a3 != 0xFFFFu) {
            float4 g = sf[a0];
            bestSc  = fmaf(g.x, ta[k], fmaf(g.y, tb[k], g.z));
            bestIdx = a0;
            g = sf[a1];
            float s1 = fmaf(g.x, ta[k], fmaf(g.y, tb[k], g.z));
            if (s1 < bestSc) { bestSc = s1; bestIdx = a1; }
            g = sf[a2];
            float s2 = fmaf(g.x, ta[k], fmaf(g.y, tb[k], g.z));
            if (s2 < bestSc) { bestSc = s2; bestIdx = a2; }
            g = sf[a3];
            float s3 = fmaf(g.x, ta[k], fmaf(g.y, tb[k], g.z));
            if (s3 < bestSc) { bestSc = s3; bestIdx = a3; }
        } else {
            // rare overflow cell
            bestSc = 1e30f; bestIdx = 0;
            const unsigned cnt = g_cnt[cell];
            if (cnt <= CAP) {
                const unsigned short* cl = &g_cand[cell * CAP];
                for (unsigned j = 0; j < cnt; j++) {
                    const unsigned bi = (unsigned)cl[j];
                    const float4 g = sf[bi];
                    const float sc = fmaf(g.x, ta[k], fmaf(g.y, tb[k], g.z));
                    if (sc < bestSc) { bestSc = sc; bestIdx = bi; }
                }
            } else {
                for (int bi = 0; bi < Q; bi++) {
                    const float4 g = sf[bi];
                    const float sc = fmaf(g.x, ta[k], fmaf(g.y, tb[k], g.z));
                    if (sc < bestSc) { bestSc = sc; bestIdx = (unsigned)bi; }
                }
            }
        }

        const float w  = sf[bestIdx].w;
        const float d0 = ia[k] - ta[k];
        const float d1 = ib[k] - tb[k];
        acc += w * fmaf(d0, d0, d1 * d1);
    }

    acc *= 0.25f;   // mean over batch b = 4

    #pragma unroll
    for (int off = 16; off; off >>= 1)
        acc += __shfl_xor_sync(0xFFFFFFFFu, acc, off);

    __shared__ float ws[8];
    if ((threadIdx.x & 31) == 0) ws[threadIdx.x >> 5] = acc;
    __syncthreads();
    if (threadIdx.x < 8) {
        float v = ws[threadIdx.x];
        #pragma unroll
        for (int off = 4; off; off >>= 1)
            v += __shfl_xor_sync(0xFFu, v, off);
        if (threadIdx.x == 0) atomicAdd(out, v);
    }
}

// ---------------------------------------------------------------------------
extern "C" void kernel_launch(void* const* d_in, const int* in_sizes, int n_in,
                              void* d_out, int out_size)
{
    const float*  input  = (const float*)d_in[0];
    const float*  target = (const float*)d_in[1];
    const float2* gamut  = (const float2*)d_in[2];   // [Q,2]
    const float*  prior  = (const float*)d_in[3];    // [Q]
    float* out = (float*)d_out;
    const int Q = in_sizes[3];                        // 313

    // LUT build also zeroes the output accumulator (ordered before loss kernel)
    build_lut_kernel<<<NCELL / 8, 256>>>(gamut, Q, out);

    // 262144 pixels, 4 per thread
    loss_kernel<<<256, 256>>>(input, target, gamut, prior, out, Q);
}